// round 11
// baseline (speedup 1.0000x reference)
#include <cuda_runtime.h>
#include <cuda_bf16.h>
#include <cstdint>

// out[r][c] = in[2r+1][2c+1], in: 8192x8192 fp32, out: 4096x4096 fp32.
// R2 read path (best: 8 front-batched __ldcs LDG.128 per thread, MLP=8)
// with 256-bit stores: each thread writes 2x st.global.v8.f32 (32B each),
// halving store instruction count; 1KB contiguous per warp-instruction.

#define N_IN   8192
#define N_OUT  4096
#define F8_ROW (N_OUT / 8)   // 512 output float8s per row
#define TPB    256
#define UNROLL 2             // F8_ROW / TPB

__device__ __forceinline__ void stg256(float* p,
                                       float4 lo, float4 hi) {
    asm volatile("st.global.v8.f32 [%0], {%1,%2,%3,%4,%5,%6,%7,%8};"
                 :: "l"(p),
                    "f"(lo.x), "f"(lo.y), "f"(lo.z), "f"(lo.w),
                    "f"(hi.x), "f"(hi.y), "f"(hi.z), "f"(hi.w)
                 : "memory");
}

__global__ __launch_bounds__(TPB) void decimate2_kernel(
    const float4* __restrict__ in, float* __restrict__ out)
{
    const int orow = blockIdx.x;
    const int tid  = threadIdx.x;

    const float4* in_row  = in  + (size_t)(2 * orow + 1) * (N_IN / 4);
    float*        out_row = out + (size_t)orow * N_OUT;

    // Each thread handles UNROLL chunks of 8 output floats (= 4 input float4s).
    float4 a[UNROLL][4];

    // Front-batched loads: 8 independent LDG.128 in flight per thread.
#pragma unroll
    for (int k = 0; k < UNROLL; k++) {
        const int oc8 = tid + k * TPB;          // output float8 index
#pragma unroll
        for (int j = 0; j < 4; j++)
            a[k][j] = __ldcs(&in_row[4 * oc8 + j]);
    }

#pragma unroll
    for (int k = 0; k < UNROLL; k++) {
        const int oc8 = tid + k * TPB;
        float4 lo, hi;
        lo.x = a[k][0].y;   // odd col 16*oc8+1
        lo.y = a[k][0].w;   // +3
        lo.z = a[k][1].y;   // +5
        lo.w = a[k][1].w;   // +7
        hi.x = a[k][2].y;   // +9
        hi.y = a[k][2].w;   // +11
        hi.z = a[k][3].y;   // +13
        hi.w = a[k][3].w;   // +15
        stg256(&out_row[8 * oc8], lo, hi);
    }
}

extern "C" void kernel_launch(void* const* d_in, const int* in_sizes, int n_in,
                              void* d_out, int out_size)
{
    const float4* in  = (const float4*)d_in[0];
    float*        out = (float*)d_out;

    decimate2_kernel<<<N_OUT, TPB>>>(in, out);
}